// round 2
// baseline (speedup 1.0000x reference)
#include <cuda_runtime.h>
#include <cstddef>

#define DIMN 1024
#define NH   16
#define DK   64
#define BATCH 4
#define QL   1024
#define KL   1024

// Scratch (device globals: allocation-free rule)
__device__ float g_Qh[BATCH*NH*QL*DK];   // [b*16+h][q][d], pre-scaled by 1/8
__device__ float g_Kh[BATCH*NH*KL*DK];
__device__ float g_Vh[BATCH*NH*KL*DK];
__device__ float g_vals[BATCH*QL*DIMN];  // attention out, [b,q, d*16+h]
__device__ float g_t1[BATCH*QL*DIMN];    // after first Wout
__device__ unsigned char g_mask8[BATCH*QL*KL]; // normalized mask (1 byte/elem)
__device__ int g_isByte;

// ---------------------------------------------------------------------------
// Mask dtype detection: if the buffer is int32 (bool upcast), every value 0/1
// has zero bytes at offsets %4 != 0. If it's a 1-byte bool, nonzero bytes
// appear at unaligned offsets (for any mask that isn't almost entirely false).
// ---------------------------------------------------------------------------
__global__ void mask_detect_kernel(const unsigned char* __restrict__ m)
{
    __shared__ int found;
    if (threadIdx.x == 0) found = 0;
    __syncthreads();
    for (int i = threadIdx.x; i < 16384; i += blockDim.x)
        if ((i & 3) && m[i]) found = 1;
    __syncthreads();
    if (threadIdx.x == 0) g_isByte = found;
}

__global__ void mask_convert_kernel(const unsigned char* __restrict__ m, int n)
{
    int i = blockIdx.x * blockDim.x + threadIdx.x;
    if (i >= n) return;
    if (g_isByte) {
        g_mask8[i] = m[i] ? 1 : 0;
    } else {
        const unsigned int* mi = (const unsigned int*)m;
        g_mask8[i] = mi[i] ? 1 : 0;
    }
}

// ---------------------------------------------------------------------------
// SGEMM: C[m,n] = sum_k A[m,k] * W[n,k]   (A:[M,K] rm, W:[N,K] rm)
// MODE 0: plain store to C[m*N+n]
// MODE 1: Q scatter  -> g_Qh[((b*16+h)*QL+q)*DK+d] * 0.125f   (h=n&15, d=n>>4)
// MODE 2: KV scatter -> g_Kh / g_Vh per-head
// Tiling: 128x128x8, 256 threads, 8x8 per thread (split 4+4)
// ---------------------------------------------------------------------------
template<int MODE>
__global__ __launch_bounds__(256)
void sgemm_kernel(const float* __restrict__ A, const float* __restrict__ W,
                  float* __restrict__ C, int M, int N, int K)
{
    __shared__ float As[8][128];
    __shared__ float Bs[8][128];

    const int m0 = blockIdx.y * 128;
    const int n0 = blockIdx.x * 128;
    const int tid = threadIdx.x;
    const int tR = tid >> 4;        // 0..15
    const int tC = tid & 15;        // 0..15

    const int lrow = tid >> 1;          // 0..127
    const int lc4  = (tid & 1) * 4;     // 0 or 4

    const float* Aptr = A + (size_t)(m0 + lrow) * K + lc4;
    const float* Wptr = W + (size_t)(n0 + lrow) * K + lc4;

    float acc[8][8];
#pragma unroll
    for (int i = 0; i < 8; i++)
#pragma unroll
        for (int j = 0; j < 8; j++) acc[i][j] = 0.f;

    for (int kk = 0; kk < K; kk += 8) {
        float4 av = *(const float4*)(Aptr + kk);
        float4 wv = *(const float4*)(Wptr + kk);
        As[lc4 + 0][lrow] = av.x;
        As[lc4 + 1][lrow] = av.y;
        As[lc4 + 2][lrow] = av.z;
        As[lc4 + 3][lrow] = av.w;
        Bs[lc4 + 0][lrow] = wv.x;
        Bs[lc4 + 1][lrow] = wv.y;
        Bs[lc4 + 2][lrow] = wv.z;
        Bs[lc4 + 3][lrow] = wv.w;
        __syncthreads();

#pragma unroll
        for (int k = 0; k < 8; k++) {
            float a[8], b[8];
            *(float4*)(a)     = *(const float4*)&As[k][tR * 4];
            *(float4*)(a + 4) = *(const float4*)&As[k][64 + tR * 4];
            *(float4*)(b)     = *(const float4*)&Bs[k][tC * 4];
            *(float4*)(b + 4) = *(const float4*)&Bs[k][64 + tC * 4];
#pragma unroll
            for (int i = 0; i < 8; i++)
#pragma unroll
                for (int j = 0; j < 8; j++)
                    acc[i][j] = fmaf(a[i], b[j], acc[i][j]);
        }
        __syncthreads();
    }

#pragma unroll
    for (int i = 0; i < 8; i++) {
        int m = m0 + ((i < 4) ? (tR * 4 + i) : (64 + tR * 4 + i - 4));
#pragma unroll
        for (int j = 0; j < 8; j++) {
            int n = n0 + ((j < 4) ? (tC * 4 + j) : (64 + tC * 4 + j - 4));
            float v = acc[i][j];
            if (MODE == 0) {
                C[(size_t)m * N + n] = v;
            } else if (MODE == 1) {
                int b = m >> 10, q = m & 1023;
                int h = n & 15, d = n >> 4;
                g_Qh[(((size_t)(b * NH + h) * QL + q) * DK) + d] = v * 0.125f;
            } else { // MODE 2
                int b = m >> 10, q = m & 1023;
                int nn = n;
                if (nn < DIMN) {
                    int h = nn & 15, d = nn >> 4;
                    g_Kh[(((size_t)(b * NH + h) * KL + q) * DK) + d] = v;
                } else {
                    nn -= DIMN;
                    int h = nn & 15, d = nn >> 4;
                    g_Vh[(((size_t)(b * NH + h) * KL + q) * DK) + d] = v;
                }
            }
        }
    }
}

// ---------------------------------------------------------------------------
// Fused attention: per block = one (b,h) and 64 q rows. Streams KV in 64-row
// tiles. Max-free softmax: P=exp(S) (scores pre-scaled via Q), l+=rowsum(P),
// O+=P@V, final O/l. Mask applied (false -> P=0).
// 256 threads: (tR,tC) 16x16, each computes a 4x4 micro-tile.
// ---------------------------------------------------------------------------
#define APAD 65
#define SMEM_ATTN (4 * 64 * APAD * (int)sizeof(float))

__global__ __launch_bounds__(256)
void attn_kernel(float* __restrict__ vals)
{
    extern __shared__ float sm[];
    float* Qt = sm;                 // [64][65]  (d-major)
    float* Kt = Qt + 64 * APAD;     // [64][65]  (d-major)
    float* Vs = Kt + 64 * APAD;     // [64][65]  (k-major)
    float* Ps = Vs + 64 * APAD;     // [64][65]  (row-major)

    const int head = blockIdx.y;          // b*16 + h
    const int b = head >> 4, h = head & 15;
    const int q0 = blockIdx.x * 64;
    const int tid = threadIdx.x;
    const int tR = tid >> 4, tC = tid & 15;

    const float* Qp = g_Qh + (size_t)head * QL * DK;
    const float* Kp = g_Kh + (size_t)head * KL * DK;
    const float* Vp = g_Vh + (size_t)head * KL * DK;

    // Load Q tile transposed (coalesced global, conflict-free smem store)
    for (int idx = tid; idx < 64 * 64; idx += 256) {
        int r = idx >> 6, d = idx & 63;
        Qt[d * APAD + r] = Qp[(size_t)(q0 + r) * DK + d];
    }

    float o[4][4];
    float l[4];
#pragma unroll
    for (int i = 0; i < 4; i++) {
        l[i] = 0.f;
#pragma unroll
        for (int j = 0; j < 4; j++) o[i][j] = 0.f;
    }

    for (int k0 = 0; k0 < KL; k0 += 64) {
        for (int idx = tid; idx < 64 * 64; idx += 256) {
            int r = idx >> 6, d = idx & 63;
            float kvv = Kp[(size_t)(k0 + r) * DK + d];
            float vvv = Vp[(size_t)(k0 + r) * DK + d];
            Kt[d * APAD + r] = kvv;
            Vs[r * APAD + d] = vvv;
        }
        __syncthreads();

        // S = Q @ K^T  (already scaled)
        float s[4][4];
#pragma unroll
        for (int i = 0; i < 4; i++)
#pragma unroll
            for (int j = 0; j < 4; j++) s[i][j] = 0.f;

#pragma unroll 8
        for (int d = 0; d < 64; d++) {
            float qv[4], kv[4];
#pragma unroll
            for (int i = 0; i < 4; i++) qv[i] = Qt[d * APAD + tR * 4 + i];
#pragma unroll
            for (int j = 0; j < 4; j++) kv[j] = Kt[d * APAD + tC * 4 + j];
#pragma unroll
            for (int i = 0; i < 4; i++)
#pragma unroll
                for (int j = 0; j < 4; j++)
                    s[i][j] = fmaf(qv[i], kv[j], s[i][j]);
        }

        // mask + exp + row-sum accumulate
#pragma unroll
        for (int i = 0; i < 4; i++) {
            int q = q0 + tR * 4 + i;
            const unsigned char* mrow = g_mask8 + ((size_t)(b * QL + q)) * KL + k0;
            float rs = 0.f;
#pragma unroll
            for (int j = 0; j < 4; j++) {
                int kc = tC * 4 + j;
                float p = mrow[kc] ? __expf(s[i][j]) : 0.f;
                s[i][j] = p;
                rs += p;
            }
            // reduce across the 16 tC lanes (half-warp groups)
#pragma unroll
            for (int off = 1; off < 16; off <<= 1)
                rs += __shfl_xor_sync(0xffffffffu, rs, off);
            l[i] += rs;
        }

        // store P
#pragma unroll
        for (int i = 0; i < 4; i++)
#pragma unroll
            for (int j = 0; j < 4; j++)
                Ps[(tR * 4 + i) * APAD + tC * 4 + j] = s[i][j];
        __syncthreads();

        // O += P @ V
#pragma unroll 8
        for (int k = 0; k < 64; k++) {
            float pv[4], vv[4];
#pragma unroll
            for (int i = 0; i < 4; i++) pv[i] = Ps[(tR * 4 + i) * APAD + k];
#pragma unroll
            for (int j = 0; j < 4; j++) vv[j] = Vs[k * APAD + tC * 4 + j];
#pragma unroll
            for (int i = 0; i < 4; i++)
#pragma unroll
                for (int j = 0; j < 4; j++)
                    o[i][j] = fmaf(pv[i], vv[j], o[i][j]);
        }
        __syncthreads();
    }

    // normalize + scatter to [b, q, d*16+h]
#pragma unroll
    for (int i = 0; i < 4; i++) {
        int q = q0 + tR * 4 + i;
        float inv = 1.f / l[i];
#pragma unroll
        for (int j = 0; j < 4; j++) {
            int d = tC * 4 + j;
            vals[((size_t)(b * QL + q)) * DIMN + d * NH + h] = o[i][j] * inv;
        }
    }
}

// ---------------------------------------------------------------------------
extern "C" void kernel_launch(void* const* d_in, const int* in_sizes, int n_in,
                              void* d_out, int out_size)
{
    const float* dec  = (const float*)d_in[0];
    const float* enc  = (const float*)d_in[1];
    const unsigned char* mask = (const unsigned char*)d_in[2];
    const float* Wq   = (const float*)d_in[3];
    const float* Wkv  = (const float*)d_in[4];
    const float* Wout = (const float*)d_in[5];
    float* out = (float*)d_out;

    float *vals_p, *t1_p;
    cudaGetSymbolAddress((void**)&vals_p, g_vals);
    cudaGetSymbolAddress((void**)&t1_p, g_t1);

    cudaFuncSetAttribute(attn_kernel,
                         cudaFuncAttributeMaxDynamicSharedMemorySize, SMEM_ATTN);

    const int M = BATCH * QL; // 4096
    const int NMASK = BATCH * QL * KL;
    dim3 blk(256);

    // Normalize mask (dtype-agnostic: int32 or byte) into g_mask8
    mask_detect_kernel<<<1, 256>>>(mask);
    mask_convert_kernel<<<(NMASK + 255) / 256, 256>>>(mask, NMASK);

    // Q = dec @ Wq^T  (scaled, scattered per-head)
    sgemm_kernel<1><<<dim3(DIMN / 128, M / 128), blk>>>(dec, Wq, nullptr, M, DIMN, DIMN);
    // KV = enc @ Wkv^T (scattered per-head, split K/V)
    sgemm_kernel<2><<<dim3(2 * DIMN / 128, M / 128), blk>>>(enc, Wkv, nullptr, M, 2 * DIMN, DIMN);
    // fused attention -> g_vals
    attn_kernel<<<dim3(QL / 64, BATCH * NH), blk, SMEM_ATTN>>>(vals_p);
    // two output projections
    sgemm_kernel<0><<<dim3(DIMN / 128, M / 128), blk>>>(vals_p, Wout, t1_p, M, DIMN, DIMN);
    sgemm_kernel<0><<<dim3(DIMN / 128, M / 128), blk>>>(t1_p, Wout, out, M, DIMN, DIMN);
}

// round 3
// speedup vs baseline: 2.5672x; 2.5672x over previous
#include <cuda_runtime.h>
#include <cstddef>

#define DIMN 1024
#define NH   16
#define DK   64
#define BATCH 4
#define QL   1024
#define KL   1024

// Scratch (device globals: allocation-free rule)
__device__ float g_Qh[BATCH*NH*QL*DK];   // [b*16+h][q][d], pre-scaled by 1/8
__device__ float g_Kh[BATCH*NH*KL*DK];
__device__ float g_Vh[BATCH*NH*KL*DK];
__device__ float g_vals[BATCH*QL*DIMN];  // attention out, [b,q, d*16+h]
__device__ float g_t1[BATCH*QL*DIMN];    // after first Wout
__device__ unsigned char g_mask8[BATCH*QL*KL];
__device__ int g_isByte;
__device__ int g_allTrue;

// ---------------------------------------------------------------------------
// tf32 helpers
// ---------------------------------------------------------------------------
__device__ __forceinline__ unsigned f2tf(float x) {
    unsigned r;
    asm("cvt.rna.tf32.f32 %0, %1;" : "=r"(r) : "f"(x));
    return r;
}

__device__ __forceinline__ void mma_tf32(float c[4], const unsigned a[4], const unsigned b[2]) {
    asm("mma.sync.aligned.m16n8k8.row.col.f32.tf32.tf32.f32 "
        "{%0,%1,%2,%3}, {%4,%5,%6,%7}, {%8,%9}, {%0,%1,%2,%3};"
        : "+f"(c[0]), "+f"(c[1]), "+f"(c[2]), "+f"(c[3])
        : "r"(a[0]), "r"(a[1]), "r"(a[2]), "r"(a[3]), "r"(b[0]), "r"(b[1]));
}

// ---------------------------------------------------------------------------
// Mask dtype detect (int32 vs byte) — int32 bool has zero bytes at off%4!=0
// ---------------------------------------------------------------------------
__global__ void mask_detect_kernel(const unsigned char* __restrict__ m)
{
    __shared__ int found;
    if (threadIdx.x == 0) { found = 0; g_allTrue = 1; }
    __syncthreads();
    for (int i = threadIdx.x; i < 16384; i += blockDim.x)
        if ((i & 3) && m[i]) found = 1;
    __syncthreads();
    if (threadIdx.x == 0) g_isByte = found;
}

__global__ void mask_convert_kernel(const unsigned char* __restrict__ m, int n)
{
    int i = blockIdx.x * blockDim.x + threadIdx.x;
    int v = 1;
    if (i < n) {
        v = g_isByte ? (m[i] ? 1 : 0) : (((const unsigned*)m)[i] ? 1 : 0);
        g_mask8[i] = (unsigned char)v;
    }
    int all = __syncthreads_and(v);
    if (!all && threadIdx.x == 0) g_allTrue = 0;
}

// ---------------------------------------------------------------------------
// TF32 tensor-core GEMM: C[m,n] = sum_k A[m,k] * W[n,k]
// BM=BN=128, BK=32, 256 threads = 8 warps (4 over M x 2 over N), warp 32x64.
// MODE 0: C[m*N+n];  MODE 1: Q scatter (*0.125);  MODE 2: KV scatter
// ---------------------------------------------------------------------------
#define LDS_T 36   // smem row stride (words): bank = 4*g + t, conflict-free

template<int MODE>
__global__ __launch_bounds__(256)
void mma_gemm(const float* __restrict__ A, const float* __restrict__ W,
              float* __restrict__ C, int M, int N, int K)
{
    __shared__ unsigned As[128 * LDS_T];
    __shared__ unsigned Bs[128 * LDS_T];

    const int tid = threadIdx.x;
    const int m0 = blockIdx.y * 128, n0 = blockIdx.x * 128;
    const int warp = tid >> 5, lane = tid & 31;
    const int wm = warp & 3, wn = warp >> 2;
    const int g = lane >> 2, t = lane & 3;

    float c[2][8][4];
#pragma unroll
    for (int mt = 0; mt < 2; mt++)
#pragma unroll
        for (int nt = 0; nt < 8; nt++)
#pragma unroll
            for (int i = 0; i < 4; i++) c[mt][nt][i] = 0.f;

    for (int kk = 0; kk < K; kk += 32) {
        // stage 128x32 of A and W, converting to tf32 (rna)
#pragma unroll
        for (int i = 0; i < 4; i++) {
            int f = tid + i * 256;            // float4 id 0..1023
            int row = f >> 3, kq = (f & 7) * 4;
            float4 av = *(const float4*)&A[(size_t)(m0 + row) * K + kk + kq];
            unsigned* da = &As[row * LDS_T + kq];
            da[0] = f2tf(av.x); da[1] = f2tf(av.y); da[2] = f2tf(av.z); da[3] = f2tf(av.w);
            float4 wv = *(const float4*)&W[(size_t)(n0 + row) * K + kk + kq];
            unsigned* db = &Bs[row * LDS_T + kq];
            db[0] = f2tf(wv.x); db[1] = f2tf(wv.y); db[2] = f2tf(wv.z); db[3] = f2tf(wv.w);
        }
        __syncthreads();

#pragma unroll
        for (int ks = 0; ks < 4; ks++) {
            const int k8 = ks * 8;
            unsigned a[2][4];
#pragma unroll
            for (int mt = 0; mt < 2; mt++) {
                int r = wm * 32 + mt * 16;
                a[mt][0] = As[(r + g) * LDS_T + k8 + t];
                a[mt][1] = As[(r + 8 + g) * LDS_T + k8 + t];
                a[mt][2] = As[(r + g) * LDS_T + k8 + 4 + t];
                a[mt][3] = As[(r + 8 + g) * LDS_T + k8 + 4 + t];
            }
#pragma unroll
            for (int nt = 0; nt < 8; nt++) {
                int cx = wn * 64 + nt * 8;
                unsigned b[2];
                b[0] = Bs[(cx + g) * LDS_T + k8 + t];
                b[1] = Bs[(cx + g) * LDS_T + k8 + 4 + t];
                mma_tf32(c[0][nt], a[0], b);
                mma_tf32(c[1][nt], a[1], b);
            }
        }
        __syncthreads();
    }

    // epilogue
#pragma unroll
    for (int mt = 0; mt < 2; mt++) {
        int r0 = m0 + wm * 32 + mt * 16 + g;
        int r1 = r0 + 8;
#pragma unroll
        for (int nt = 0; nt < 8; nt++) {
            int col = n0 + wn * 64 + nt * 8 + 2 * t;
            float v00 = c[mt][nt][0], v01 = c[mt][nt][1];
            float v10 = c[mt][nt][2], v11 = c[mt][nt][3];
            if (MODE == 0) {
                *(float2*)&C[(size_t)r0 * N + col] = make_float2(v00, v01);
                *(float2*)&C[(size_t)r1 * N + col] = make_float2(v10, v11);
            } else if (MODE == 1) {
#pragma unroll
                for (int e = 0; e < 4; e++) {
                    int m = (e < 2) ? r0 : r1;
                    int n = col + (e & 1);
                    float v = (e == 0) ? v00 : (e == 1) ? v01 : (e == 2) ? v10 : v11;
                    int b = m >> 10, q = m & 1023;
                    int h = n & 15, d = n >> 4;
                    g_Qh[(((size_t)(b * NH + h) * QL + q) * DK) + d] = v * 0.125f;
                }
            } else {
#pragma unroll
                for (int e = 0; e < 4; e++) {
                    int m = (e < 2) ? r0 : r1;
                    int n = col + (e & 1);
                    float v = (e == 0) ? v00 : (e == 1) ? v01 : (e == 2) ? v10 : v11;
                    int b = m >> 10, q = m & 1023;
                    if (n < DIMN) {
                        int h = n & 15, d = n >> 4;
                        g_Kh[(((size_t)(b * NH + h) * KL + q) * DK) + d] = v;
                    } else {
                        int nn = n - DIMN;
                        int h = nn & 15, d = nn >> 4;
                        g_Vh[(((size_t)(b * NH + h) * KL + q) * DK) + d] = v;
                    }
                }
            }
        }
    }
}

// ---------------------------------------------------------------------------
// Fused attention with tf32 mma. Block = (b,h) x 64 q rows, 128 threads
// (4 warps, warp = 16 q rows). KV streamed in 64-key tiles.
// Max-free softmax (Q pre-scaled): P=exp(S), l+=rowsum, O+=P@V, O/l at end.
// Smem: Qs/Ks row-major [64][68], Vt transposed [d][key] [64][68],
//       Ps [q][k] [64][68], mask tile 64x64 bytes. All frag loads
//       bank-conflict-free (bank = 4g+t pattern).
// ---------------------------------------------------------------------------
#define ATT_LD 68
#define SMEM_ATTN (4 * 64 * ATT_LD * 4 + 64 * 64)

__global__ __launch_bounds__(128)
void attn_kernel(float* __restrict__ vals)
{
    extern __shared__ unsigned smU[];
    unsigned* Qs = smU;
    unsigned* Ks = Qs + 64 * ATT_LD;
    unsigned* Vt = Ks + 64 * ATT_LD;
    unsigned* Ps = Vt + 64 * ATT_LD;
    unsigned char* Ms = (unsigned char*)(Ps + 64 * ATT_LD);

    const int head = blockIdx.y;
    const int b = head >> 4, h = head & 15;
    const int q0 = blockIdx.x * 64;
    const int tid = threadIdx.x;
    const int w = tid >> 5, lane = tid & 31;
    const int g = lane >> 2, t = lane & 3;
    const int wq0 = w * 16;
    const int allTrue = g_allTrue;

    const float* Qp = g_Qh + (size_t)head * QL * DK;
    const float* Kp = g_Kh + (size_t)head * KL * DK;
    const float* Vp = g_Vh + (size_t)head * KL * DK;

    // stage Q tile (64 x 64), tf32
#pragma unroll
    for (int i = 0; i < 8; i++) {
        int f = tid + i * 128;
        int row = f >> 4, dq = (f & 15) * 4;
        float4 qv = *(const float4*)&Qp[(size_t)(q0 + row) * DK + dq];
        unsigned* d = &Qs[row * ATT_LD + dq];
        d[0] = f2tf(qv.x); d[1] = f2tf(qv.y); d[2] = f2tf(qv.z); d[3] = f2tf(qv.w);
    }

    float o[8][4];
#pragma unroll
    for (int nt = 0; nt < 8; nt++)
#pragma unroll
        for (int i = 0; i < 4; i++) o[nt][i] = 0.f;
    float l0 = 0.f, l1 = 0.f;

    for (int k0 = 0; k0 < KL; k0 += 64) {
        // stage K (row-major) and V (transposed), tf32
#pragma unroll
        for (int i = 0; i < 8; i++) {
            int f = tid + i * 128;
            int row = f >> 4, dq = (f & 15) * 4;
            float4 kv = *(const float4*)&Kp[(size_t)(k0 + row) * DK + dq];
            unsigned* d = &Ks[row * ATT_LD + dq];
            d[0] = f2tf(kv.x); d[1] = f2tf(kv.y); d[2] = f2tf(kv.z); d[3] = f2tf(kv.w);
            float4 vv = *(const float4*)&Vp[(size_t)(k0 + row) * DK + dq];
            Vt[(dq + 0) * ATT_LD + row] = f2tf(vv.x);
            Vt[(dq + 1) * ATT_LD + row] = f2tf(vv.y);
            Vt[(dq + 2) * ATT_LD + row] = f2tf(vv.z);
            Vt[(dq + 3) * ATT_LD + row] = f2tf(vv.w);
        }
        if (!allTrue) {
            const unsigned* mrow = (const unsigned*)(g_mask8 + ((size_t)(b * QL + q0)) * KL + k0);
#pragma unroll
            for (int i = 0; i < 8; i++) {
                int f = tid + i * 128;
                int qr = f >> 4, kq = f & 15;
                ((unsigned*)Ms)[qr * 16 + kq] =
                    *(const unsigned*)((const unsigned char*)mrow + (size_t)qr * KL + kq * 4);
            }
        }
        __syncthreads();

        // S = Q @ K^T
        float s[8][4];
#pragma unroll
        for (int nt = 0; nt < 8; nt++)
#pragma unroll
            for (int i = 0; i < 4; i++) s[nt][i] = 0.f;

#pragma unroll
        for (int ks = 0; ks < 8; ks++) {
            const int k8 = ks * 8;
            unsigned a[4];
            a[0] = Qs[(wq0 + g) * ATT_LD + k8 + t];
            a[1] = Qs[(wq0 + 8 + g) * ATT_LD + k8 + t];
            a[2] = Qs[(wq0 + g) * ATT_LD + k8 + 4 + t];
            a[3] = Qs[(wq0 + 8 + g) * ATT_LD + k8 + 4 + t];
#pragma unroll
            for (int nt = 0; nt < 8; nt++) {
                unsigned bf[2];
                bf[0] = Ks[(nt * 8 + g) * ATT_LD + k8 + t];
                bf[1] = Ks[(nt * 8 + g) * ATT_LD + k8 + 4 + t];
                mma_tf32(s[nt], a, bf);
            }
        }

        // mask + exp + rowsum, write P (tf32) to smem
        int qr0 = wq0 + g, qr1 = wq0 + 8 + g;
        float rs0 = 0.f, rs1 = 0.f;
#pragma unroll
        for (int nt = 0; nt < 8; nt++) {
            int kc = nt * 8 + 2 * t;
            float p00, p01, p10, p11;
            if (allTrue) {
                p00 = __expf(s[nt][0]); p01 = __expf(s[nt][1]);
                p10 = __expf(s[nt][2]); p11 = __expf(s[nt][3]);
            } else {
                p00 = Ms[qr0 * 64 + kc]     ? __expf(s[nt][0]) : 0.f;
                p01 = Ms[qr0 * 64 + kc + 1] ? __expf(s[nt][1]) : 0.f;
                p10 = Ms[qr1 * 64 + kc]     ? __expf(s[nt][2]) : 0.f;
                p11 = Ms[qr1 * 64 + kc + 1] ? __expf(s[nt][3]) : 0.f;
            }
            rs0 += p00 + p01;
            rs1 += p10 + p11;
            uint2 w0 = make_uint2(f2tf(p00), f2tf(p01));
            uint2 w1 = make_uint2(f2tf(p10), f2tf(p11));
            *(uint2*)&Ps[qr0 * ATT_LD + kc] = w0;
            *(uint2*)&Ps[qr1 * ATT_LD + kc] = w1;
        }
        // reduce across the quad (lanes sharing the same rows)
        rs0 += __shfl_xor_sync(0xffffffffu, rs0, 1);
        rs0 += __shfl_xor_sync(0xffffffffu, rs0, 2);
        rs1 += __shfl_xor_sync(0xffffffffu, rs1, 1);
        rs1 += __shfl_xor_sync(0xffffffffu, rs1, 2);
        l0 += rs0;
        l1 += rs1;
        __syncwarp();   // Ps is produced & consumed within this warp only

        // O += P @ V
#pragma unroll
        for (int ks = 0; ks < 8; ks++) {
            const int k8 = ks * 8;
            unsigned a[4];
            a[0] = Ps[(wq0 + g) * ATT_LD + k8 + t];
            a[1] = Ps[(wq0 + 8 + g) * ATT_LD + k8 + t];
            a[2] = Ps[(wq0 + g) * ATT_LD + k8 + 4 + t];
            a[3] = Ps[(wq0 + 8 + g) * ATT_LD + k8 + 4 + t];
#pragma unroll
            for (int nt = 0; nt < 8; nt++) {
                unsigned bf[2];
                bf[0] = Vt[(nt * 8 + g) * ATT_LD + k8 + t];
                bf[1] = Vt[(nt * 8 + g) * ATT_LD + k8 + 4 + t];
                mma_tf32(o[nt], a, bf);
            }
        }
        __syncthreads();  // K/V/M tiles reused next iteration
    }

    // normalize + scatter to [b, q, d*16+h]
    float inv0 = 1.f / l0, inv1 = 1.f / l1;
    int qa = q0 + wq0 + g, qb = qa + 8;
#pragma unroll
    for (int nt = 0; nt < 8; nt++) {
        int d = nt * 8 + 2 * t;
        float* base0 = &vals[((size_t)(b * QL + qa)) * DIMN + d * NH + h];
        float* base1 = &vals[((size_t)(b * QL + qb)) * DIMN + d * NH + h];
        base0[0]  = o[nt][0] * inv0;
        base0[NH] = o[nt][1] * inv0;
        base1[0]  = o[nt][2] * inv1;
        base1[NH] = o[nt][3] * inv1;
    }
}

// ---------------------------------------------------------------------------
extern "C" void kernel_launch(void* const* d_in, const int* in_sizes, int n_in,
                              void* d_out, int out_size)
{
    const float* dec  = (const float*)d_in[0];
    const float* enc  = (const float*)d_in[1];
    const unsigned char* mask = (const unsigned char*)d_in[2];
    const float* Wq   = (const float*)d_in[3];
    const float* Wkv  = (const float*)d_in[4];
    const float* Wout = (const float*)d_in[5];
    float* out = (float*)d_out;

    float *vals_p, *t1_p;
    cudaGetSymbolAddress((void**)&vals_p, g_vals);
    cudaGetSymbolAddress((void**)&t1_p, g_t1);

    cudaFuncSetAttribute(attn_kernel,
                         cudaFuncAttributeMaxDynamicSharedMemorySize, SMEM_ATTN);

    const int M = BATCH * QL; // 4096
    const int NMASK = BATCH * QL * KL;
    dim3 blk(256);

    mask_detect_kernel<<<1, 256>>>(mask);
    mask_convert_kernel<<<(NMASK + 255) / 256, 256>>>(mask, NMASK);

    // Q = dec @ Wq^T  (scaled, scattered per-head)
    mma_gemm<1><<<dim3(DIMN / 128, M / 128), blk>>>(dec, Wq, nullptr, M, DIMN, DIMN);
    // KV = enc @ Wkv^T (scattered per-head, split K/V)
    mma_gemm<2><<<dim3(2 * DIMN / 128, M / 128), blk>>>(enc, Wkv, nullptr, M, 2 * DIMN, DIMN);
    // fused attention -> g_vals
    attn_kernel<<<dim3(QL / 64, BATCH * NH), dim3(128), SMEM_ATTN>>>(vals_p);
    // two output projections
    mma_gemm<0><<<dim3(DIMN / 128, M / 128), blk>>>(vals_p, Wout, t1_p, M, DIMN, DIMN);
    mma_gemm<0><<<dim3(DIMN / 128, M / 128), blk>>>(t1_p, Wout, out, M, DIMN, DIMN);
}